// round 13
// baseline (speedup 1.0000x reference)
#include <cuda_runtime.h>
#include <cuda_bf16.h>

// CASSI forward A^T(A(x)); coded aperture is band-broadcast (phi[l]==phi2d):
//   y2[b,m,j]    = sum_{l : 0<=j-2l<N} x[b,l,m,j-2l]*phi2d[m,j-2l]
//   out[b,l,m,n] = phi2d[m,n] * y2[b,m,n+2l]
// L=28, M=N=256, STRIDE=2, n_out=310.
//
// R13: two-kernel split at y2 (10.5MB __device__ scratch).
//   Kernel A: per (b,m) row — load x*phi into smem, diagonal-reduce, write
//             y2 row to global. ~pure READ stream (235MB in / 10MB out).
//   Kernel B: per (b,m) row — stage y2 row (+2-shifted copy) from global,
//             out = phi * y2[n+2l]. ~pure WRITE stream (10MB in / 235MB out).

#define LBANDS 28
#define NCOLS  256
#define NC4    (NCOLS / 4)                        // 64 float4 per row
#define NOUT   (NCOLS + 2 * (LBANDS - 1))         // 310
#define THREADS 256
#define MNFIX  (NCOLS * NCOLS)
#define BAND4  (MNFIX / 4)                        // float4 stride between bands
#define Y2PITCH 320                               // padded y2 row (floats)

// y2 scratch: 32*256 rows * 320 floats = 10.5 MB (+pad)
__device__ float g_y2[32 * 256 * Y2PITCH + 16];

// ---------------- Kernel A: x -> y2 (read stream) ----------------
__global__ __launch_bounds__(THREADS, 6)
void cassi_a(const float4* __restrict__ x4,
             const float4* __restrict__ phi4,
             int LMN4 /* L*M*N/4 */)
{
    __shared__ float prod[LBANDS * NCOLS];   // 28 KB
    float4* prod4 = reinterpret_cast<float4*>(prod);

    const int m   = blockIdx.x;
    const int b   = blockIdx.y;
    const int tid = threadIdx.x;

    const int lsub = tid >> 6;
    const int c    = tid & 63;

    const float4 pv = phi4[m * NC4 + c];     // band-independent mask row

    // phase 1: prod = x*phi -> smem
    {
        int xo = b * LMN4 + m * NC4 + lsub * BAND4 + c;
        int so = lsub * NC4 + c;
#pragma unroll
        for (int k = 0; k < LBANDS / 4; ++k) {
            const float4 xv = x4[xo];
            float4 pr;
            pr.x = xv.x * pv.x; pr.y = xv.y * pv.y;
            pr.z = xv.z * pv.z; pr.w = xv.w * pv.w;
            prod4[so] = pr;
            xo += 4 * BAND4; so += 4 * NC4;
        }
    }
    __syncthreads();

    // phase 2: diagonal reduce, write y2 pair straight to global
    {
        const int j = tid << 1;              // 0,2,...,510
        if (j < NOUT) {
            float sx = 0.0f, sy = 0.0f;
            const float* pb = prod + j;
            if (j >= 2 * (LBANDS - 1) && j < NCOLS) {
#pragma unroll
                for (int l = 0; l < LBANDS; ++l) {
                    const float2 p =
                        *reinterpret_cast<const float2*>(pb + l * (NCOLS - 2));
                    sx += p.x; sy += p.y;
                }
            } else {
                const int lmin = (j >= NCOLS) ? ((j - (NCOLS - 2)) >> 1) : 0;
                const int jh   = j >> 1;
                const int lmax = jh < (LBANDS - 1) ? jh : (LBANDS - 1);
                for (int l = lmin; l <= lmax; ++l) {
                    const float2 p =
                        *reinterpret_cast<const float2*>(pb + l * (NCOLS - 2));
                    sx += p.x; sy += p.y;
                }
            }
            *reinterpret_cast<float2*>(
                g_y2 + (b * NCOLS + m) * Y2PITCH + j) = make_float2(sx, sy);
        }
    }
}

// ---------------- Kernel B: y2 -> out (write stream) ----------------
__global__ __launch_bounds__(THREADS, 6)
void cassi_b(const float4* __restrict__ phi4,
             float4* __restrict__ out4,
             int LMN4)
{
    __shared__ float y2 [320];
    __shared__ float y2s[320];               // y2s[j] == y2[j+2]

    const int m   = blockIdx.x;
    const int b   = blockIdx.y;
    const int tid = threadIdx.x;

    const int lsub = tid >> 6;
    const int c    = tid & 63;

    const float* grow = g_y2 + (b * NCOLS + m) * Y2PITCH;

    // stage y2 + shifted copy from global (independent, one barrier)
    if (tid < 80) {
        reinterpret_cast<float4*>(y2)[tid] =
            reinterpret_cast<const float4*>(grow)[tid];
    } else if (tid < 234) {                  // t' = tid-80 in [0,154): y2s[0..307]
        const int t2 = (tid - 80) << 1;
        *reinterpret_cast<float2*>(y2s + t2) =
            *reinterpret_cast<const float2*>(grow + t2 + 2);
    }

    const float4 pv = phi4[m * NC4 + c];     // overlaps with staging loads
    __syncthreads();

    // phase 3: out = phi * y2[n+2l]
    {
        const float* ybase = (lsub & 1) ? y2s : y2;
        int yo4 = ((c << 2) + 2 * lsub - ((lsub & 1) << 1)) >> 2;
        int oo  = b * LMN4 + m * NC4 + lsub * BAND4 + c;
#pragma unroll
        for (int k = 0; k < LBANDS / 4; ++k) {
            const float4 yv = reinterpret_cast<const float4*>(ybase)[yo4];
            float4 ov;
            ov.x = pv.x * yv.x; ov.y = pv.y * yv.y;
            ov.z = pv.z * yv.z; ov.w = pv.w * yv.w;
            out4[oo] = ov;
            oo += 4 * BAND4;
            yo4 += 2;
        }
    }
}

extern "C" void kernel_launch(void* const* d_in, const int* in_sizes, int n_in,
                              void* d_out, int out_size)
{
    const float4* x4   = (const float4*)d_in[0];   // [B, L, M, N]
    const float4* phi4 = (const float4*)d_in[1];   // [L, M, N] (band-broadcast)
    float4* out4 = (float4*)d_out;

    const int LMN  = in_sizes[1];        // L*M*N
    const int B    = in_sizes[0] / LMN;  // batch (32)
    const int LMN4 = LMN / 4;

    dim3 grid(NCOLS /* M */, B);
    cassi_a<<<grid, THREADS>>>(x4, phi4, LMN4);
    cassi_b<<<grid, THREADS>>>(phi4, out4, LMN4);
}

// round 14
// speedup vs baseline: 1.1534x; 1.1534x over previous
#include <cuda_runtime.h>
#include <cuda_bf16.h>

// CASSI forward A^T(A(x)); coded aperture is band-broadcast (phi[l]==phi2d):
//   y2[b,m,j]    = sum_{l : 0<=j-2l<N} x[b,l,m,j-2l]*phi2d[m,j-2l]
//   out[b,l,m,n] = phi2d[m,n] * y2[b,m,n+2l]
// One CTA per (b,m) row. L=28, M=N=256, STRIDE=2, n_out=310.
//
// R14 = R9 (champion structure: 6 CTAs/SM, phi-in-register, LDS.64 phase 2,
// LDS.128 phase 3) + streaming cache hints: x read-once via __ldcs, out
// write-once via __stcs — keeps L2 for the reused phi rows / boundary sectors.

#define LBANDS 28
#define NCOLS  256
#define NC4    (NCOLS / 4)                        // 64 float4 per row
#define NOUT   (NCOLS + 2 * (LBANDS - 1))         // 310
#define THREADS 256
#define MNFIX  (NCOLS * NCOLS)
#define BAND4  (MNFIX / 4)                        // float4 stride between bands

__global__ __launch_bounds__(THREADS, 6)
void cassi_kernel(const float4* __restrict__ x4,
                  const float4* __restrict__ phi4,
                  float4* __restrict__ out4,
                  int LMN4 /* L*M*N/4 */)
{
    __shared__ float prod[LBANDS * NCOLS];   // 28 KB
    __shared__ float y2 [320];
    __shared__ float y2s[320];               // y2s[j] == y2[j+2]
    float4* prod4 = reinterpret_cast<float4*>(prod);

    const int m   = blockIdx.x;
    const int b   = blockIdx.y;
    const int tid = threadIdx.x;

    const int lsub = tid >> 6;        // 0..3, uniform per warp-pair
    const int c    = tid & 63;        // float4 column 0..63

    const int xrow4 = b * LMN4 + m * NC4;        // x/out row base (float4 units)

    // phi2d row element for this thread's 4 columns — band-independent,
    // default cache policy (reused across 32 batches -> L2-resident).
    const float4 pv = phi4[m * NC4 + c];

    // ---- phase 1: prod = x*phi -> smem (streaming LDG.128 + STS.128) ----
    {
        int xo = xrow4 + lsub * BAND4 + c;
        int so = lsub * NC4 + c;
#pragma unroll
        for (int k = 0; k < LBANDS / 4; ++k) {
            const float4 xv = __ldcs(&x4[xo]);   // read-once: evict-first
            float4 pr;
            pr.x = xv.x * pv.x; pr.y = xv.y * pv.y;
            pr.z = xv.z * pv.z; pr.w = xv.w * pv.w;
            prod4[so] = pr;
            xo += 4 * BAND4; so += 4 * NC4;
        }
    }
    __syncthreads();

    // ---- phase 2: y2[j],y2[j+1] (j even) via aligned LDS.64 ----
    // Even j: lmin/lmax identical for j and j+1; prod address 2-aligned.
    {
        const int j = tid << 1;                   // 0,2,...,510
        if (j < NOUT) {
            float sx = 0.0f, sy = 0.0f;
            const float* pb = prod + j;
            if (j >= 2 * (LBANDS - 1) && j < NCOLS) {
#pragma unroll
                for (int l = 0; l < LBANDS; ++l) {
                    const float2 p =
                        *reinterpret_cast<const float2*>(pb + l * (NCOLS - 2));
                    sx += p.x; sy += p.y;
                }
            } else {
                const int lmin = (j >= NCOLS) ? ((j - (NCOLS - 2)) >> 1) : 0;
                const int jh   = j >> 1;
                const int lmax = jh < (LBANDS - 1) ? jh : (LBANDS - 1);
                for (int l = lmin; l <= lmax; ++l) {
                    const float2 p =
                        *reinterpret_cast<const float2*>(pb + l * (NCOLS - 2));
                    sx += p.x; sy += p.y;
                }
            }
            *reinterpret_cast<float2*>(y2 + j) = make_float2(sx, sy);
            if (j >= 2)
                *reinterpret_cast<float2*>(y2s + j - 2) = make_float2(sx, sy);
        }
    }
    __syncthreads();

    // ---- phase 3: out = phi * y2[n+2l]; streaming STG.128 ----
    {
        // band l = 4k + lsub; parity of l == parity of lsub (warp-uniform)
        const float* ybase = (lsub & 1) ? y2s : y2;
        // aligned float4 index covering y2[4c + 2l] (shift folded into y2s)
        int yo4 = ((c << 2) + 2 * lsub - ((lsub & 1) << 1)) >> 2;
        int oo  = xrow4 + lsub * BAND4 + c;
#pragma unroll
        for (int k = 0; k < LBANDS / 4; ++k) {
            const float4 yv = reinterpret_cast<const float4*>(ybase)[yo4];
            float4 ov;
            ov.x = pv.x * yv.x; ov.y = pv.y * yv.y;
            ov.z = pv.z * yv.z; ov.w = pv.w * yv.w;
            __stcs(&out4[oo], ov);               // write-once: evict-first
            oo += 4 * BAND4;
            yo4 += 2;                      // 4 bands * stride 2 = 8 floats
        }
    }
}

extern "C" void kernel_launch(void* const* d_in, const int* in_sizes, int n_in,
                              void* d_out, int out_size)
{
    const float4* x4   = (const float4*)d_in[0];   // [B, L, M, N]
    const float4* phi4 = (const float4*)d_in[1];   // [L, M, N] (band-broadcast)
    float4* out4 = (float4*)d_out;

    const int LMN  = in_sizes[1];        // L*M*N
    const int B    = in_sizes[0] / LMN;  // batch
    const int LMN4 = LMN / 4;

    dim3 grid(NCOLS /* M */, B);
    cassi_kernel<<<grid, THREADS>>>(x4, phi4, out4, LMN4);
}

// round 15
// speedup vs baseline: 1.2131x; 1.0518x over previous
#include <cuda_runtime.h>
#include <cuda_bf16.h>

// CASSI forward A^T(A(x)); coded aperture is band-broadcast (phi[l]==phi2d):
//   y2[b,m,j]    = sum_{l : 0<=j-2l<N} x[b,l,m,j-2l]*phi2d[m,j-2l]
//   out[b,l,m,n] = phi2d[m,n] * y2[b,m,n+2l]
// One CTA per (b,m) row. L=28, M=N=256, STRIDE=2, n_out=310.
//
// FINAL (== R9 champion, 75.8us): session-validated optimum.
//  - one CTA per row; prod = x*phi staged via SMEM float4 (read x once, coalesced)
//  - phi band-broadcast -> single float4 register reused in phases 1 and 3
//  - phase 2: even/odd j pair shares band range -> aligned LDS.64 diagonal sums
//  - phase 3: dual y2/y2s copies make every read an aligned LDS.128
//  - 6 CTAs/SM (31.25KB smem, 39 regs): measured occ x MLP sweet spot
//    (5 CTAs: 81.9us, 7 CTAs: 88.2us, pipelined/split/hinted variants all worse)

#define LBANDS 28
#define NCOLS  256
#define NC4    (NCOLS / 4)                        // 64 float4 per row
#define NOUT   (NCOLS + 2 * (LBANDS - 1))         // 310
#define THREADS 256

__global__ __launch_bounds__(THREADS, 6)
void cassi_kernel(const float4* __restrict__ x4,
                  const float4* __restrict__ phi4,
                  float4* __restrict__ out4,
                  int M, int LMN4 /* L*M*N/4 */)
{
    __shared__ float prod[LBANDS * NCOLS];   // 28 KB
    __shared__ float y2 [320];
    __shared__ float y2s[320];               // y2s[j] == y2[j+2]
    float4* prod4 = reinterpret_cast<float4*>(prod);

    const int m   = blockIdx.x;
    const int b   = blockIdx.y;
    const int tid = threadIdx.x;

    const int lsub = tid >> 6;        // 0..3, uniform per warp-pair
    const int c    = tid & 63;        // float4 column 0..63

    const int band4 = M * NC4;                   // float4 stride between bands
    const int xrow4 = b * LMN4 + m * NC4;        // x/out row base (float4 units)

    // phi2d row element for this thread's 4 columns — band-independent.
    const float4 pv = phi4[m * NC4 + c];

    // ---- phase 1: prod = x*phi -> smem (LDG.128 x1 + STS.128 x1 per band) ----
    {
        int xo = xrow4 + lsub * band4 + c;
        int so = lsub * NC4 + c;
#pragma unroll
        for (int k = 0; k < LBANDS / 4; ++k) {
            const float4 xv = x4[xo];
            float4 pr;
            pr.x = xv.x * pv.x; pr.y = xv.y * pv.y;
            pr.z = xv.z * pv.z; pr.w = xv.w * pv.w;
            prod4[so] = pr;
            xo += 4 * band4; so += 4 * NC4;
        }
    }
    __syncthreads();

    // ---- phase 2: y2[j],y2[j+1] (j even) via aligned LDS.64 ----
    // For even j: lmin/lmax identical for j and j+1; prod address 2-aligned.
    {
        const int j = tid << 1;                   // 0,2,...,510
        if (j < NOUT) {
            const int lmin = (j >= NCOLS) ? ((j - (NCOLS - 2)) >> 1) : 0;
            const int jh   = j >> 1;
            const int lmax = jh < (LBANDS - 1) ? jh : (LBANDS - 1);
            float sx = 0.0f, sy = 0.0f;
            const float* pb = prod + j;
            for (int l = lmin; l <= lmax; ++l) {
                const float2 p =
                    *reinterpret_cast<const float2*>(pb + l * (NCOLS - 2));
                sx += p.x; sy += p.y;
            }
            y2[j]     = sx;
            y2[j + 1] = sy;
            if (j >= 2) {
                y2s[j - 2] = sx;
                y2s[j - 1] = sy;
            }
        }
    }
    __syncthreads();

    // ---- phase 3: out = phi * y2[n+2l]; phi from register, y2 via LDS.128 ----
    {
        // band l = 4k + lsub; parity of l == parity of lsub (warp-uniform)
        const float* ybase = (lsub & 1) ? y2s : y2;
        // aligned float4 index covering y2[4c + 2l] (shift folded into y2s)
        int yo4 = ((c << 2) + 2 * lsub - ((lsub & 1) << 1)) >> 2;
        int oo  = xrow4 + lsub * band4 + c;
#pragma unroll
        for (int k = 0; k < LBANDS / 4; ++k) {
            const float4 yv = reinterpret_cast<const float4*>(ybase)[yo4];
            float4 ov;
            ov.x = pv.x * yv.x; ov.y = pv.y * yv.y;
            ov.z = pv.z * yv.z; ov.w = pv.w * yv.w;
            out4[oo] = ov;
            oo += 4 * band4;
            yo4 += 2;                      // 4 bands * stride 2 = 8 floats
        }
    }
}

extern "C" void kernel_launch(void* const* d_in, const int* in_sizes, int n_in,
                              void* d_out, int out_size)
{
    const float4* x4   = (const float4*)d_in[0];   // [B, L, M, N]
    const float4* phi4 = (const float4*)d_in[1];   // [L, M, N] (band-broadcast)
    float4* out4 = (float4*)d_out;

    const int LMN  = in_sizes[1];        // L*M*N
    const int M    = NCOLS;              // M == 256
    const int B    = in_sizes[0] / LMN;  // batch
    const int LMN4 = LMN / 4;

    dim3 grid(M, B);
    cassi_kernel<<<grid, THREADS>>>(x4, phi4, out4, M, LMN4);
}